// round 12
// baseline (speedup 1.0000x reference)
#include <cuda_runtime.h>

#define B_    64
#define C_    768
#define HW_   784      // 28*28
#define HID_  192      // C/4
#define HW4_  196      // HW/4  (float4 per (b,c) row)

#define NCH_  2
#define BPC_  (B_ / NCH_)                        // 32 batches / chunk = 77 MB of x
#define ROWS_PER_CHUNK  (BPC_ * C_)              // 24576 (b,c) rows
#define F4_PER_CHUNK    (ROWS_PER_CHUNK * HW4_)  // 4,816,896 float4
#define PAIRS_PER_CHUNK (F4_PER_CHUNK / 2)       // 2,408,448 (exactly /256)

// scratch (no device allocation allowed)
__device__ float g_pooled[B_ * C_];
__device__ float g_s[B_ * C_];

// ---------------------------------------------------------------------------
// pool(ch): warp per (b,c) row (196 float4). Default cache policy so the
// chunk of x lands in L2 and STAYS there for scale(ch). 6 unconditional +
// 1 predicated LDG.128 per lane -> MLP 7.
// ---------------------------------------------------------------------------
__global__ void pool_kernel(const float* __restrict__ x, int row_base) {
    unsigned warp = (blockIdx.x * blockDim.x + threadIdx.x) >> 5;   // exact grid
    unsigned lane = threadIdx.x & 31u;
    unsigned row  = (unsigned)row_base + warp;

    const float4* p = reinterpret_cast<const float4*>(x) + (size_t)row * HW4_;
    float4 a0 = p[lane];
    float4 a1 = p[lane + 32];
    float4 a2 = p[lane + 64];
    float4 a3 = p[lane + 96];
    float4 a4 = p[lane + 128];
    float4 a5 = p[lane + 160];
    float extra = 0.f;
    if (lane < 4) {                      // indices 192..195
        float4 v = p[lane + 192];
        extra = (v.x + v.y) + (v.z + v.w);
    }
    float s01 = (a0.x + a0.y) + (a0.z + a0.w) + (a1.x + a1.y) + (a1.z + a1.w);
    float s23 = (a2.x + a2.y) + (a2.z + a2.w) + (a3.x + a3.y) + (a3.z + a3.w);
    float s45 = (a4.x + a4.y) + (a4.z + a4.w) + (a5.x + a5.y) + (a5.z + a5.w);
    float sum = (s01 + s23) + (s45 + extra);

    #pragma unroll
    for (int o = 16; o > 0; o >>= 1)
        sum += __shfl_xor_sync(0xffffffffu, sum, o);
    if (lane == 0)
        g_pooled[row] = sum * (1.0f / HW_);
}

// ---------------------------------------------------------------------------
// fc(ch): one block per batch element (BPC_ blocks, 256 threads).
//   h = relu(pooled @ w1^T + b1); s = hardsigmoid(h @ w2^T + b2)
// w1/w2 (589 KB each) are L2-resident after the first chunk.
// ---------------------------------------------------------------------------
__global__ void fc_kernel(const float* __restrict__ w1, const float* __restrict__ b1,
                          const float* __restrict__ w2, const float* __restrict__ b2,
                          int batch_base) {
    __shared__ float sp[C_];
    __shared__ float sh[HID_];
    const int b = batch_base + (int)blockIdx.x;
    const unsigned t    = threadIdx.x;
    const unsigned lane = t & 31u;
    const unsigned wid  = t >> 5;          // 0..7

    for (unsigned i = t; i < C_; i += 256)
        sp[i] = g_pooled[b * C_ + i];
    __syncthreads();

    // fc1: warp per h output (8 warps x 24 outputs)
    for (unsigned h = wid; h < HID_; h += 8) {
        const float4* wv = reinterpret_cast<const float4*>(w1 + h * C_);
        const float4* pv = reinterpret_cast<const float4*>(sp);
        float acc = 0.f;
        #pragma unroll
        for (int k = 0; k < 6; k++) {
            float4 a = pv[lane + 32 * k];
            float4 w = wv[lane + 32 * k];
            acc += a.x * w.x + a.y * w.y + a.z * w.z + a.w * w.w;
        }
        #pragma unroll
        for (int o = 16; o > 0; o >>= 1)
            acc += __shfl_xor_sync(0xffffffffu, acc, o);
        if (lane == 0)
            sh[h] = fmaxf(acc + b1[h], 0.f);
    }
    __syncthreads();

    // fc2: warp per c output (8 warps x 96 outputs)
    for (unsigned c = wid; c < C_; c += 8) {
        const float4* wv = reinterpret_cast<const float4*>(w2 + c * HID_);
        const float4* hv = reinterpret_cast<const float4*>(sh);
        float4 a = hv[lane];
        float4 w = wv[lane];
        float acc = a.x * w.x + a.y * w.y + a.z * w.z + a.w * w.w;
        if (lane < 16) {
            a = hv[lane + 32];
            w = wv[lane + 32];
            acc += a.x * w.x + a.y * w.y + a.z * w.z + a.w * w.w;
        }
        #pragma unroll
        for (int o = 16; o > 0; o >>= 1)
            acc += __shfl_xor_sync(0xffffffffu, acc, o);
        if (lane == 0)
            g_s[b * C_ + c] = __saturatef((acc + b2[c]) * (1.0f / 6.0f) + 0.5f);
    }
}

// ---------------------------------------------------------------------------
// scale(ch): out = x * s[b,c]. x for this chunk is L2-resident (just pooled).
// Thread owns one 32B pair of float4 (HW4_ even -> one s per thread).
// __ldcs: last use of x (evict-first after hit). __stcs: write-only stream,
// evict-first so out doesn't evict the NEXT chunk's x.
// ---------------------------------------------------------------------------
__global__ void scale_kernel(const float* __restrict__ x, float* __restrict__ out,
                             unsigned f4_base) {
    unsigned j  = blockIdx.x * blockDim.x + threadIdx.x;    // pair idx in chunk
    unsigned f0 = f4_base + 2u * j;

    float s = g_s[f0 / HW4_];
    const float4* xp = reinterpret_cast<const float4*>(x);
    float4*       op = reinterpret_cast<float4*>(out);

    float4 v0 = __ldcs(xp + f0);
    float4 v1 = __ldcs(xp + f0 + 1);
    v0.x *= s; v0.y *= s; v0.z *= s; v0.w *= s;
    v1.x *= s; v1.y *= s; v1.z *= s; v1.w *= s;
    __stcs(op + f0,     v0);
    __stcs(op + f0 + 1, v1);
}

// ---------------------------------------------------------------------------
extern "C" void kernel_launch(void* const* d_in, const int* in_sizes, int n_in,
                              void* d_out, int out_size) {
    const float* x  = (const float*)d_in[0];
    const float* w1 = (const float*)d_in[1];
    const float* b1 = (const float*)d_in[2];
    const float* w2 = (const float*)d_in[3];
    const float* b2 = (const float*)d_in[4];
    float* out = (float*)d_out;

    for (int ch = 0; ch < NCH_; ch++) {
        int row_base = ch * ROWS_PER_CHUNK;
        // pool: warp per row; 24576 rows / 8 warps-per-block = 3072 blocks
        pool_kernel<<<ROWS_PER_CHUNK / 8, 256>>>(x, row_base);
        // fc: block per batch
        fc_kernel<<<BPC_, 256>>>(w1, b1, w2, b2, ch * BPC_);
        // scale: 2,408,448 pairs / 256 = 9408 blocks (exact)
        scale_kernel<<<PAIRS_PER_CHUNK / 256, 256>>>(
            x, out, (unsigned)ch * (unsigned)F4_PER_CHUNK);
    }
}

// round 14
// speedup vs baseline: 2.5984x; 2.5984x over previous
#include <cuda_runtime.h>

#define B_   64
#define C_   768
#define HW_  784      // 28*28
#define HID_ 192      // C/4
#define HW4_ 196      // HW/4  (float4 per (b,c) row)

// scratch (no device allocation allowed)
__device__ float g_pooled[B_ * C_];
__device__ float g_h[B_ * HID_];
__device__ float g_s[B_ * C_];

// ---------------------------------------------------------------------------
// Kernel 1: global average pool. One warp per (b,c) row (196 float4).
// 6 unconditional + 1 predicated LDG.128 per lane -> MLP 7. (R4-proven: 28us)
// ---------------------------------------------------------------------------
__global__ void pool_kernel(const float* __restrict__ x) {
    unsigned warp = (blockIdx.x * blockDim.x + threadIdx.x) >> 5;   // exact grid
    unsigned lane = threadIdx.x & 31u;

    const float4* p = reinterpret_cast<const float4*>(x) + (size_t)warp * HW4_;
    float4 a0 = p[lane];
    float4 a1 = p[lane + 32];
    float4 a2 = p[lane + 64];
    float4 a3 = p[lane + 96];
    float4 a4 = p[lane + 128];
    float4 a5 = p[lane + 160];
    float extra = 0.f;
    if (lane < 4) {                      // indices 192..195
        float4 v = p[lane + 192];
        extra = (v.x + v.y) + (v.z + v.w);
    }
    float s01 = (a0.x + a0.y) + (a0.z + a0.w) + (a1.x + a1.y) + (a1.z + a1.w);
    float s23 = (a2.x + a2.y) + (a2.z + a2.w) + (a3.x + a3.y) + (a3.z + a3.w);
    float s45 = (a4.x + a4.y) + (a4.z + a4.w) + (a5.x + a5.y) + (a5.z + a5.w);
    float sum = (s01 + s23) + (s45 + extra);

    #pragma unroll
    for (int o = 16; o > 0; o >>= 1)
        sum += __shfl_xor_sync(0xffffffffu, sum, o);
    if (lane == 0)
        g_pooled[warp] = sum * (1.0f / HW_);
}

// ---------------------------------------------------------------------------
// Kernel 2a: h = relu(pooled @ w1^T + b1). One warp per (b,h) output.
// ---------------------------------------------------------------------------
__global__ void fc1_kernel(const float* __restrict__ w1, const float* __restrict__ b1) {
    unsigned gw   = (blockIdx.x * blockDim.x + threadIdx.x) >> 5;   // 0..12287
    unsigned lane = threadIdx.x & 31u;
    unsigned b = gw / HID_;
    unsigned h = gw % HID_;

    const float4* pv = reinterpret_cast<const float4*>(g_pooled + b * C_);
    const float4* wv = reinterpret_cast<const float4*>(w1 + h * C_);
    float acc = 0.f;
    #pragma unroll
    for (int k = 0; k < 6; k++) {
        float4 a = pv[lane + 32 * k];
        float4 w = wv[lane + 32 * k];
        acc += a.x * w.x + a.y * w.y + a.z * w.z + a.w * w.w;
    }
    #pragma unroll
    for (int o = 16; o > 0; o >>= 1)
        acc += __shfl_xor_sync(0xffffffffu, acc, o);
    if (lane == 0)
        g_h[gw] = fmaxf(acc + b1[h], 0.f);
}

// ---------------------------------------------------------------------------
// Kernel 2b: s = hardsigmoid(h @ w2^T + b2). One warp per (b,c) output.
// ---------------------------------------------------------------------------
__global__ void fc2_kernel(const float* __restrict__ w2, const float* __restrict__ b2) {
    unsigned gw   = (blockIdx.x * blockDim.x + threadIdx.x) >> 5;   // 0..49151
    unsigned lane = threadIdx.x & 31u;
    unsigned b = gw / C_;
    unsigned c = gw % C_;

    const float4* hv = reinterpret_cast<const float4*>(g_h + b * HID_);
    const float4* wv = reinterpret_cast<const float4*>(w2 + c * HID_);
    float4 a = hv[lane];
    float4 w = wv[lane];
    float acc = a.x * w.x + a.y * w.y + a.z * w.z + a.w * w.w;
    if (lane < 16) {
        a = hv[lane + 32];
        w = wv[lane + 32];
        acc += a.x * w.x + a.y * w.y + a.z * w.z + a.w * w.w;
    }
    #pragma unroll
    for (int o = 16; o > 0; o >>= 1)
        acc += __shfl_xor_sync(0xffffffffu, acc, o);
    if (lane == 0)
        g_s[gw] = __saturatef((acc + b2[c]) * (1.0f / 6.0f) + 0.5f);
}

// ---------------------------------------------------------------------------
// Kernel 3: out = x * s[b,c]. Each thread owns FOUR consecutive float4 (64B);
// 196 % 4 == 0 so all four share one channel -> one s, one division.
// REVERSED block order to harvest the L2-resident tail of x left by pool.
// __ldcs: last-use read of x. __stwt: WRITE-THROUGH, NO L2 ALLOCATE — the
// out-stream must not evict the resident x window (R4's __stcs still
// allocated and cost us ~half the potential L2 hits).
// ---------------------------------------------------------------------------
__global__ void scale_kernel(const float* __restrict__ x, float* __restrict__ out) {
    unsigned j  = (gridDim.x - 1u - blockIdx.x) * blockDim.x + threadIdx.x;
    unsigned f0 = j * 4u;                                   // first float4 idx

    float s = g_s[f0 / HW4_];
    const float4* xp = reinterpret_cast<const float4*>(x);
    float4*       op = reinterpret_cast<float4*>(out);

    float4 v0 = __ldcs(xp + f0);
    float4 v1 = __ldcs(xp + f0 + 1);
    float4 v2 = __ldcs(xp + f0 + 2);
    float4 v3 = __ldcs(xp + f0 + 3);
    v0.x *= s; v0.y *= s; v0.z *= s; v0.w *= s;
    v1.x *= s; v1.y *= s; v1.z *= s; v1.w *= s;
    v2.x *= s; v2.y *= s; v2.z *= s; v2.w *= s;
    v3.x *= s; v3.y *= s; v3.z *= s; v3.w *= s;
    __stwt(op + f0,     v0);
    __stwt(op + f0 + 1, v1);
    __stwt(op + f0 + 2, v2);
    __stwt(op + f0 + 3, v3);
}

// ---------------------------------------------------------------------------
extern "C" void kernel_launch(void* const* d_in, const int* in_sizes, int n_in,
                              void* d_out, int out_size) {
    const float* x  = (const float*)d_in[0];
    const float* w1 = (const float*)d_in[1];
    const float* b1 = (const float*)d_in[2];
    const float* w2 = (const float*)d_in[3];
    const float* b2 = (const float*)d_in[4];
    float* out = (float*)d_out;

    pool_kernel<<<(B_ * C_) / 8, 256>>>(x);              // 6144 blocks, warp/row
    fc1_kernel<<<(B_ * HID_) / 8, 256>>>(w1, b1);        // 1536 blocks, warp/out
    fc2_kernel<<<(B_ * C_) / 8, 256>>>(w2, b2);          // 6144 blocks, warp/out
    // scale: 9,633,792 float4 / 4 per thread / 256 = 9408 blocks (exact)
    const unsigned nthreads4 = (unsigned)(B_ * C_ * HW4_) / 4u;
    scale_kernel<<<nthreads4 / 256, 256>>>(x, out);
}